// round 14
// baseline (speedup 1.0000x reference)
#include <cuda_runtime.h>
#include <cuda_fp16.h>
#include <cstdint>

// ---------------------------------------------------------------------------
// HyperTransposeConv via fp16 mma.sync implicit GEMM.
// R14: K-chunk 64 (was 32) -> half the __syncthreads/wait_group overhead and
// 128-MMA runs between barriers. 3-stage cp.async, both operands streamed
// (B via NHWC fp16 + zfill). Geometry: 256 thr, 8 warps of 32x64, CTA 128x128.
// ---------------------------------------------------------------------------

#define CIN  512
#define COUT 256
#define HIN  64
#define HOUT 128

__constant__ int c_IDX[8][8] = {
    {0,1,2,1,4,3,2,3},
    {1,0,3,2,5,4,1,2},
    {2,1,0,1,6,5,4,3},
    {3,2,1,0,7,6,5,4},
    {4,3,2,3,0,1,2,1},
    {5,4,1,2,1,0,3,2},
    {6,5,4,3,2,1,0,1},
    {7,6,5,4,3,2,1,0}};
// sign[i][j] = (j <= i) ? +1 : -1

__device__ __half g_Wh[4u * 256 * 2048];       // [par][co][k], k=(t,u,ci)
__device__ __half g_xt[8u * 64 * 64 * 512];    // NHWC fp16: [b][y][x][ci]
__device__ float g_bias[COUT];

// ---------------------------------------------------------------------------
__global__ void build_wh(const float* __restrict__ W) {
    int e = blockIdx.x * 256 + threadIdx.x;
    if (e >= 4 * 256 * 2048) return;
    int k   = e & 2047;
    int co  = (e >> 11) & 255;
    int par = e >> 19;
    int py = par >> 1, px = par & 1;
    int tu = k >> 9, ci = k & 511;          // k = (t,u) major, ci minor
    int t = tu >> 1, u = tu & 1;
    int i = co >> 5, c = co & 31;
    int j = ci >> 6, a = ci & 63;
    int kh = 3 - py - 2 * t, kw = 3 - px - 2 * u;
    float sgn = (j <= i) ? 1.0f : -1.0f;
    g_Wh[e] = __float2half_rn(
        sgn * W[((c_IDX[i][j] * 64 + a) * 32 + c) * 16 + kh * 4 + kw]);
}

__global__ void build_bias(const float* __restrict__ b) {
    int t = threadIdx.x;
    if (t >= COUT) return;
    int i = t >> 5, c = t & 31;
    float s = 0.f;
#pragma unroll
    for (int j = 0; j < 8; ++j)
        s += ((j <= i) ? 1.0f : -1.0f) * b[c_IDX[i][j] * 32 + c];
    g_bias[t] = s;
}

// NCHW fp32 -> NHWC fp16 transpose, smem-tiled. grid (8, 64, 8), block 256.
__global__ void build_xt(const float* __restrict__ x) {
    __shared__ float s[64][65];
    const int tid = threadIdx.x;
    const int cb = blockIdx.x, y = blockIdx.y, b = blockIdx.z;
    const float* src = x + ((size_t)(b * 512 + cb * 64) * 64 + y) * 64;
#pragma unroll
    for (int i = 0; i < 16; ++i) {
        int ci = i * 4 + (tid >> 6);
        int xx = tid & 63;
        s[ci][xx] = src[(size_t)ci * 4096 + xx];
    }
    __syncthreads();
    const int xx = tid >> 2, c0 = (tid & 3) * 16;
    __half2 buf[8];
#pragma unroll
    for (int j = 0; j < 8; ++j)
        buf[j] = __floats2half2_rn(s[c0 + 2 * j][xx], s[c0 + 2 * j + 1][xx]);
    __half2* dp = reinterpret_cast<__half2*>(
        g_xt + (((size_t)(b * 64 + y) * 64 + xx) * 512) + cb * 64 + c0);
#pragma unroll
    for (int j = 0; j < 8; ++j) dp[j] = buf[j];
}

// ---------------------------------------------------------------------------
#define PITCH 144                  // 64 halves (128B) + 16B pad, conflict-free
#define AST  (128 * PITCH)         // 18432
#define BSTG (128 * PITCH)
#define BOFF (3 * AST)
#define SMEM_REQ (3 * AST + 3 * BSTG)   // 110592

#define LDSM4(R0, R1, R2, R3, ADDR)                                          \
    asm volatile("ldmatrix.sync.aligned.m8n8.x4.shared.b16 {%0,%1,%2,%3}, [%4];" \
                 : "=r"(R0), "=r"(R1), "=r"(R2), "=r"(R3) : "r"(ADDR))

#define MMA16816(C, A, B0v, B1v)                                             \
    asm volatile("mma.sync.aligned.m16n8k16.row.col.f32.f16.f16.f32 "        \
                 "{%0,%1,%2,%3}, {%4,%5,%6,%7}, {%8,%9}, {%0,%1,%2,%3};"     \
                 : "+f"((C)[0]), "+f"((C)[1]), "+f"((C)[2]), "+f"((C)[3])    \
                 : "r"((A)[0]), "r"((A)[1]), "r"((A)[2]), "r"((A)[3]),       \
                   "r"(B0v), "r"(B1v))

#define CPA16(DST, SRC)                                                      \
    asm volatile("cp.async.cg.shared.global [%0], [%1], 16;"                 \
                 :: "r"(DST), "l"(SRC))
#define CPA16Z(DST, SRC, SZ)                                                 \
    asm volatile("cp.async.cg.shared.global [%0], [%1], 16, %2;"             \
                 :: "r"(DST), "l"(SRC), "r"(SZ))

__global__ __launch_bounds__(256, 2)
void hconv_hmma(float* __restrict__ out) {
    extern __shared__ char smem[];
    uint32_t sb;
    asm("{ .reg .u64 t; cvta.to.shared.u64 t, %1; cvt.u32.u64 %0, t; }"
        : "=r"(sb) : "l"(smem));
    const uint32_t Abase = sb, Bbase = sb + BOFF;

    const int tid = threadIdx.x;
    const int l   = tid & 31, wid = tid >> 5;
    const int co0 = blockIdx.x * 128;
    const int y0  = blockIdx.y * 2;
    const int z   = blockIdx.z;
    const int b   = z >> 2;
    const int par = z & 3, py = par >> 1, px = par & 1;

    // ---- feed mappings: thread owns row (tid>>1), 64B half (tid&1) ----
    const int frow = tid >> 1, fhalf = tid & 1;
    const __half* wsrc =
        g_Wh + ((size_t)(par * 256 + co0 + frow)) * 2048 + fhalf * 32;
    const uint32_t adst = Abase + (uint32_t)(frow * PITCH + fhalf * 64);
    const uint32_t bdst = Bbase + (uint32_t)(frow * PITCH + fhalf * 64);

    // B pixel geometry for row n = frow
    const int yy = frow >> 6, xq = frow & 63;
    const int iyb = y0 + yy - 1 + py;      // + t
    const int ixb = xq + px - 1;           // + u
    const __half* xtb = g_xt + (size_t)b * (64 * 64 * 512) + fhalf * 32;

    // warp tiles 32x64 (4m x 2n warps)
    const int m0 = (wid >> 1) * 32;
    const int n0 = (wid & 1) * 64;
    const uint32_t loff = (uint32_t)((l & 15) * PITCH + (l >> 4) * 16);

    float acc[2][8][4];
#pragma unroll
    for (int a = 0; a < 2; ++a)
#pragma unroll
        for (int f = 0; f < 8; ++f)
#pragma unroll
            for (int e = 0; e < 4; ++e) acc[a][f][e] = 0.f;

    // issue cp.async for chunk CH (64 k-values) into stage ST
#define FEED(CH, ST)                                                         \
    do {                                                                     \
        const int c_ = (CH);                                                 \
        const int tu_ = c_ >> 3, cb_ = c_ & 7;  /* 8 chunks per (t,u) */     \
        const int t_ = tu_ >> 1, u_ = tu_ & 1;                               \
        const __half* as_ = wsrc + c_ * 64;                                  \
        _Pragma("unroll")                                                    \
        for (int e = 0; e < 4; ++e)                                          \
            CPA16(adst + (ST) * AST + e * 16, as_ + e * 8);                  \
        const int iy_ = iyb + t_, ix_ = ixb + u_;                            \
        const bool v_ = ((unsigned)iy_ < HIN) && ((unsigned)ix_ < HIN);      \
        const uint32_t sz_ = v_ ? 16u : 0u;                                  \
        const __half* bs_ = xtb +                                            \
            ((size_t)((v_ ? iy_ : 0) * 64 + (v_ ? ix_ : 0)) * 512) +         \
            cb_ * 64;                                                        \
        _Pragma("unroll")                                                    \
        for (int e = 0; e < 4; ++e)                                          \
            CPA16Z(bdst + (ST) * BSTG + e * 16, bs_ + e * 8, sz_);           \
    } while (0)

    // ---------------- prologue ----------------
    FEED(0, 0);
    asm volatile("cp.async.commit_group;");
    FEED(1, 1);
    asm volatile("cp.async.commit_group;");

    // ---------------- main loop: 32 K-chunks of 64 ----------------
#pragma unroll 1
    for (int i = 0; i < 32; ++i) {
        asm volatile("cp.async.wait_group 1;");
        __syncthreads();

        if (i + 2 < 32) FEED(i + 2, (i + 2) % 3);
        asm volatile("cp.async.commit_group;");

        const uint32_t As = Abase + (i % 3) * AST;
        const uint32_t Bs = Bbase + (i % 3) * BSTG;
#pragma unroll
        for (int ks = 0; ks < 4; ++ks) {
            uint32_t af[2][4];
#pragma unroll
            for (int mm = 0; mm < 2; ++mm)
                LDSM4(af[mm][0], af[mm][1], af[mm][2], af[mm][3],
                      As + (uint32_t)((m0 + mm * 16) * PITCH + ks * 32) + loff);
            uint32_t bf[8][2];
#pragma unroll
            for (int nb = 0; nb < 4; ++nb) {
                uint32_t r0, r1, r2, r3;
                LDSM4(r0, r1, r2, r3,
                      Bs + (uint32_t)((n0 + nb * 16) * PITCH + ks * 32) + loff);
                bf[nb * 2][0] = r0;     bf[nb * 2][1] = r2;
                bf[nb * 2 + 1][0] = r1; bf[nb * 2 + 1][1] = r3;
            }
#pragma unroll
            for (int mm = 0; mm < 2; ++mm)
#pragma unroll
                for (int f = 0; f < 8; ++f)
                    MMA16816(acc[mm][f], af[mm], bf[f][0], bf[f][1]);
        }
    }

    // ---------------- epilogue ----------------
#pragma unroll
    for (int mm = 0; mm < 2; ++mm) {
#pragma unroll
        for (int eh = 0; eh < 2; ++eh) {
            const int m  = m0 + mm * 16 + (l >> 2) + eh * 8;
            const int co = co0 + m;
            const float bias = g_bias[co];
            float* ob = out + ((size_t)(b * COUT + co) * HOUT) * HOUT;
#pragma unroll
            for (int f = 0; f < 8; ++f) {
#pragma unroll
                for (int ew = 0; ew < 2; ++ew) {
                    const int np = n0 + f * 8 + 2 * (l & 3) + ew;
                    const int oy = 2 * (y0 + (np >> 6)) + py;
                    const int ox = 2 * (np & 63) + px;
                    ob[(size_t)oy * HOUT + ox] = acc[mm][f][eh * 2 + ew] + bias;
                }
            }
        }
    }
}

// ---------------------------------------------------------------------------
extern "C" void kernel_launch(void* const* d_in, const int* in_sizes, int n_in,
                              void* d_out, int out_size) {
    const float* x = (const float*)d_in[0];   // [8,512,64,64]
    const float* W = (const float*)d_in[1];   // [8,64,32,4,4]
    const float* b = (const float*)d_in[2];   // [8,32]
    float* out = (float*)d_out;               // [8,256,128,128]

    build_wh<<<(4 * 256 * 2048 + 255) / 256, 256>>>(W);
    build_bias<<<1, 256>>>(b);
    build_xt<<<dim3(8, 64, 8), 256>>>(x);

    cudaFuncSetAttribute(hconv_hmma,
                         cudaFuncAttributeMaxDynamicSharedMemorySize, SMEM_REQ);
    dim3 grid(2, 32, 32);
    hconv_hmma<<<grid, 256, SMEM_REQ>>>(out);
}

// round 16
// speedup vs baseline: 1.1960x; 1.1960x over previous
#include <cuda_runtime.h>
#include <cuda_fp16.h>
#include <cstdint>

// ---------------------------------------------------------------------------
// HyperTransposeConv via fp16 mma.sync implicit GEMM.
// R15 = R13 (best: 603us) + 4-stage cp.async pipeline with wait_group 2 so
// the consumer wait is on a group issued 3 chunks earlier (latency slack),
// + vectorized build_xt stores.
// Geometry: 256 thr, 8 warps of 32x64, CTA 128x128, K-chunk 32, 2 CTA/SM.
// ---------------------------------------------------------------------------

#define CIN  512
#define COUT 256
#define HIN  64
#define HOUT 128

__constant__ int c_IDX[8][8] = {
    {0,1,2,1,4,3,2,3},
    {1,0,3,2,5,4,1,2},
    {2,1,0,1,6,5,4,3},
    {3,2,1,0,7,6,5,4},
    {4,3,2,3,0,1,2,1},
    {5,4,1,2,1,0,3,2},
    {6,5,4,3,2,1,0,1},
    {7,6,5,4,3,2,1,0}};
// sign[i][j] = (j <= i) ? +1 : -1

__device__ __half g_Wh[4u * 256 * 2048];       // [par][co][k], k=(t,u,ci)
__device__ __half g_xt[8u * 64 * 64 * 512];    // NHWC fp16: [b][y][x][ci]
__device__ float g_bias[COUT];

// ---------------------------------------------------------------------------
__global__ void build_wh(const float* __restrict__ W) {
    int e = blockIdx.x * 256 + threadIdx.x;
    if (e >= 4 * 256 * 2048) return;
    int k   = e & 2047;
    int co  = (e >> 11) & 255;
    int par = e >> 19;
    int py = par >> 1, px = par & 1;
    int tu = k >> 9, ci = k & 511;          // k = (t,u) major, ci minor
    int t = tu >> 1, u = tu & 1;
    int i = co >> 5, c = co & 31;
    int j = ci >> 6, a = ci & 63;
    int kh = 3 - py - 2 * t, kw = 3 - px - 2 * u;
    float sgn = (j <= i) ? 1.0f : -1.0f;
    g_Wh[e] = __float2half_rn(
        sgn * W[((c_IDX[i][j] * 64 + a) * 32 + c) * 16 + kh * 4 + kw]);
}

__global__ void build_bias(const float* __restrict__ b) {
    int t = threadIdx.x;
    if (t >= COUT) return;
    int i = t >> 5, c = t & 31;
    float s = 0.f;
#pragma unroll
    for (int j = 0; j < 8; ++j)
        s += ((j <= i) ? 1.0f : -1.0f) * b[c_IDX[i][j] * 32 + c];
    g_bias[t] = s;
}

// NCHW fp32 -> NHWC fp16 transpose, smem-tiled. grid (8, 64, 8), block 256.
__global__ void build_xt(const float* __restrict__ x) {
    __shared__ float s[64][65];
    const int tid = threadIdx.x;
    const int cb = blockIdx.x, y = blockIdx.y, b = blockIdx.z;
    const float* src = x + ((size_t)(b * 512 + cb * 64) * 64 + y) * 64;
#pragma unroll
    for (int i = 0; i < 16; ++i) {
        int ci = i * 4 + (tid >> 6);
        int xx = tid & 63;
        s[ci][xx] = src[(size_t)ci * 4096 + xx];
    }
    __syncthreads();
    const int xx = tid >> 2, c0 = (tid & 3) * 16;
    uint32_t buf[8];
#pragma unroll
    for (int j = 0; j < 8; ++j) {
        __half2 h = __floats2half2_rn(s[c0 + 2 * j][xx], s[c0 + 2 * j + 1][xx]);
        buf[j] = *reinterpret_cast<uint32_t*>(&h);
    }
    uint4* dp = reinterpret_cast<uint4*>(
        g_xt + (((size_t)(b * 64 + y) * 64 + xx) * 512) + cb * 64 + c0);
    dp[0] = make_uint4(buf[0], buf[1], buf[2], buf[3]);
    dp[1] = make_uint4(buf[4], buf[5], buf[6], buf[7]);
}

// ---------------------------------------------------------------------------
#define PITCH 80                   // 32 halves (64B) + 16B pad, conflict-free
#define AST  (128 * PITCH)         // 10240
#define BSTG (128 * PITCH)
#define NSTG 4
#define BOFF (NSTG * AST)
#define SMEM_REQ (NSTG * AST + NSTG * BSTG)   // 81920

#define LDSM4(R0, R1, R2, R3, ADDR)                                          \
    asm volatile("ldmatrix.sync.aligned.m8n8.x4.shared.b16 {%0,%1,%2,%3}, [%4];" \
                 : "=r"(R0), "=r"(R1), "=r"(R2), "=r"(R3) : "r"(ADDR))

#define MMA16816(C, A, B0v, B1v)                                             \
    asm volatile("mma.sync.aligned.m16n8k16.row.col.f32.f16.f16.f32 "        \
                 "{%0,%1,%2,%3}, {%4,%5,%6,%7}, {%8,%9}, {%0,%1,%2,%3};"     \
                 : "+f"((C)[0]), "+f"((C)[1]), "+f"((C)[2]), "+f"((C)[3])    \
                 : "r"((A)[0]), "r"((A)[1]), "r"((A)[2]), "r"((A)[3]),       \
                   "r"(B0v), "r"(B1v))

#define CPA16(DST, SRC)                                                      \
    asm volatile("cp.async.cg.shared.global [%0], [%1], 16;"                 \
                 :: "r"(DST), "l"(SRC))
#define CPA16Z(DST, SRC, SZ)                                                 \
    asm volatile("cp.async.cg.shared.global [%0], [%1], 16, %2;"             \
                 :: "r"(DST), "l"(SRC), "r"(SZ))

__global__ __launch_bounds__(256, 2)
void hconv_hmma(float* __restrict__ out) {
    extern __shared__ char smem[];
    uint32_t sb;
    asm("{ .reg .u64 t; cvta.to.shared.u64 t, %1; cvt.u32.u64 %0, t; }"
        : "=r"(sb) : "l"(smem));
    const uint32_t Abase = sb, Bbase = sb + BOFF;

    const int tid = threadIdx.x;
    const int l   = tid & 31, wid = tid >> 5;
    const int co0 = blockIdx.x * 128;
    const int y0  = blockIdx.y * 2;
    const int z   = blockIdx.z;
    const int b   = z >> 2;
    const int par = z & 3, py = par >> 1, px = par & 1;

    // ---- feed mappings: thread owns row (tid>>1), 16B half (tid&1) ----
    const int frow = tid >> 1, fhalf = tid & 1;
    const __half* wsrc =
        g_Wh + ((size_t)(par * 256 + co0 + frow)) * 2048 + fhalf * 16;
    const uint32_t adst = Abase + (uint32_t)(frow * PITCH + fhalf * 32);
    const uint32_t bdst = Bbase + (uint32_t)(frow * PITCH + fhalf * 32);

    // B pixel geometry for row n = frow
    const int yy = frow >> 6, xq = frow & 63;
    const int iyb = y0 + yy - 1 + py;      // + t
    const int ixb = xq + px - 1;           // + u
    const __half* xtb = g_xt + (size_t)b * (64 * 64 * 512) + fhalf * 16;

    // warp tiles 32x64 (4m x 2n warps)
    const int m0 = (wid >> 1) * 32;
    const int n0 = (wid & 1) * 64;
    const uint32_t loff = (uint32_t)((l & 15) * PITCH + (l >> 4) * 16);

    float acc[2][8][4];
#pragma unroll
    for (int a = 0; a < 2; ++a)
#pragma unroll
        for (int f = 0; f < 8; ++f)
#pragma unroll
            for (int e = 0; e < 4; ++e) acc[a][f][e] = 0.f;

    // issue cp.async for chunk CH (32 k-values) into stage ST
#define FEED(CH, ST)                                                         \
    do {                                                                     \
        const int c_ = (CH);                                                 \
        const int tu_ = c_ >> 4, cib_ = c_ & 15;                             \
        const int t_ = tu_ >> 1, u_ = tu_ & 1;                               \
        const __half* as_ = wsrc + c_ * 32;                                  \
        CPA16(adst + (ST) * AST, as_);                                       \
        CPA16(adst + (ST) * AST + 16, as_ + 8);                              \
        const int iy_ = iyb + t_, ix_ = ixb + u_;                            \
        const bool v_ = ((unsigned)iy_ < HIN) && ((unsigned)ix_ < HIN);      \
        const uint32_t sz_ = v_ ? 16u : 0u;                                  \
        const __half* bs_ = xtb +                                            \
            ((size_t)((v_ ? iy_ : 0) * 64 + (v_ ? ix_ : 0)) * 512) +         \
            cib_ * 32;                                                       \
        CPA16Z(bdst + (ST) * BSTG, bs_, sz_);                                \
        CPA16Z(bdst + (ST) * BSTG + 16, bs_ + 8, sz_);                       \
    } while (0)

    // ---------------- prologue: fill 3 stages ----------------
    FEED(0, 0);
    asm volatile("cp.async.commit_group;");
    FEED(1, 1);
    asm volatile("cp.async.commit_group;");
    FEED(2, 2);
    asm volatile("cp.async.commit_group;");

    // ---------------- main loop: 64 K-chunks of 32 ----------------
#pragma unroll 1
    for (int i = 0; i < 64; ++i) {
        asm volatile("cp.async.wait_group 2;");
        __syncthreads();

        if (i + 3 < 64) FEED(i + 3, (i + 3) & 3);
        asm volatile("cp.async.commit_group;");

        const uint32_t As = Abase + (i & 3) * AST;
        const uint32_t Bs = Bbase + (i & 3) * BSTG;
#pragma unroll
        for (int ks = 0; ks < 2; ++ks) {
            uint32_t af[2][4];
#pragma unroll
            for (int mm = 0; mm < 2; ++mm)
                LDSM4(af[mm][0], af[mm][1], af[mm][2], af[mm][3],
                      As + (uint32_t)((m0 + mm * 16) * PITCH + ks * 32) + loff);
            uint32_t bf[8][2];
#pragma unroll
            for (int nb = 0; nb < 4; ++nb) {
                uint32_t r0, r1, r2, r3;
                LDSM4(r0, r1, r2, r3,
                      Bs + (uint32_t)((n0 + nb * 16) * PITCH + ks * 32) + loff);
                bf[nb * 2][0] = r0;     bf[nb * 2][1] = r2;
                bf[nb * 2 + 1][0] = r1; bf[nb * 2 + 1][1] = r3;
            }
#pragma unroll
            for (int mm = 0; mm < 2; ++mm)
#pragma unroll
                for (int f = 0; f < 8; ++f)
                    MMA16816(acc[mm][f], af[mm], bf[f][0], bf[f][1]);
        }
    }

    // ---------------- epilogue ----------------
#pragma unroll
    for (int mm = 0; mm < 2; ++mm) {
#pragma unroll
        for (int eh = 0; eh < 2; ++eh) {
            const int m  = m0 + mm * 16 + (l >> 2) + eh * 8;
            const int co = co0 + m;
            const float bias = g_bias[co];
            float* ob = out + ((size_t)(b * COUT + co) * HOUT) * HOUT;
#pragma unroll
            for (int f = 0; f < 8; ++f) {
#pragma unroll
                for (int ew = 0; ew < 2; ++ew) {
                    const int np = n0 + f * 8 + 2 * (l & 3) + ew;
                    const int oy = 2 * (y0 + (np >> 6)) + py;
                    const int ox = 2 * (np & 63) + px;
                    ob[(size_t)oy * HOUT + ox] = acc[mm][f][eh * 2 + ew] + bias;
                }
            }
        }
    }
}

// ---------------------------------------------------------------------------
extern "C" void kernel_launch(void* const* d_in, const int* in_sizes, int n_in,
                              void* d_out, int out_size) {
    const float* x = (const float*)d_in[0];   // [8,512,64,64]
    const float* W = (const float*)d_in[1];   // [8,64,32,4,4]
    const float* b = (const float*)d_in[2];   // [8,32]
    float* out = (float*)d_out;               // [8,256,128,128]

    build_wh<<<(4 * 256 * 2048 + 255) / 256, 256>>>(W);
    build_bias<<<1, 256>>>(b);
    build_xt<<<dim3(8, 64, 8), 256>>>(x);

    cudaFuncSetAttribute(hconv_hmma,
                         cudaFuncAttributeMaxDynamicSharedMemorySize, SMEM_REQ);
    dim3 grid(2, 32, 32);
    hconv_hmma<<<grid, 256, SMEM_REQ>>>(out);
}